// round 1
// baseline (speedup 1.0000x reference)
#include <cuda_runtime.h>
#include <math.h>

// Problem constants (fixed by reference)
#define BB 256
#define TT 72
#define NN 5
#define FF_IN 10
#define HH 4
#define CC 32
#define DD 128
#define FFD 256
#define NHEAD 4
#define DHEAD 32
#define BT (BB*TT)   // 18432

// ---------------- device scratch (no allocations allowed) ----------------
__device__ float d_z[BT*DD];
__device__ float d_qkv[BT*3*DD];
__device__ float d_o[BT*DD];
__device__ float d_ff[BT*FFD];
__device__ float d_tmp[BT*DD];
__device__ float d_Anorm[NN*NN];
__device__ int   d_src2[64];
__device__ int   d_dst2[64];

// ---------------- graph build (single thread, trivial) ----------------
__global__ void build_graph_kernel(const int* __restrict__ ei, int E) {
    if (threadIdx.x != 0 || blockIdx.x != 0) return;
    float A[NN][NN];
    for (int i = 0; i < NN*NN; i++) ((float*)A)[i] = 0.f;
    for (int e = 0; e < E; e++) {
        int s = ei[e];
        int d = ei[E + e];
        A[d][s] += 1.f;
        d_src2[e] = s; d_dst2[e] = d;
    }
    for (int n = 0; n < NN; n++) {
        A[n][n] += 1.f;
        d_src2[E + n] = n; d_dst2[E + n] = n;
    }
    float dinv[NN];
    for (int n = 0; n < NN; n++) {
        float s = 0.f;
        for (int j = 0; j < NN; j++) s += A[n][j];
        dinv[n] = (s > 0.f) ? (1.f / sqrtf(s)) : 0.f;
    }
    for (int i = 0; i < NN; i++)
        for (int j = 0; j < NN; j++)
            d_Anorm[i*NN + j] = dinv[i] * A[i][j] * dinv[j];
}

// ---------------- block reduce (128 threads) ----------------
__device__ __forceinline__ float blockReduceSum128(float v, float* sred) {
    __syncthreads();
    #pragma unroll
    for (int o = 16; o > 0; o >>= 1) v += __shfl_xor_sync(0xffffffffu, v, o);
    if ((threadIdx.x & 31) == 0) sred[threadIdx.x >> 5] = v;
    __syncthreads();
    return sred[0] + sred[1] + sred[2] + sred[3];
}

// ---------------- fused GCN + GAT + LN + node-mean + PE ----------------
__global__ void gcn_gat_kernel(
    const float* __restrict__ x,
    const float* __restrict__ gcn_w, const float* __restrict__ gcn_b,
    const float* __restrict__ gat_w, const float* __restrict__ a_src,
    const float* __restrict__ a_dst, const float* __restrict__ gat_b,
    const float* __restrict__ gln_g, const float* __restrict__ gln_b,
    float* __restrict__ z, int E2)
{
    int bt = blockIdx.x;
    int tid = threadIdx.x;  // 128

    __shared__ float sx[NN][FF_IN];
    __shared__ float sxw[NN][64];
    __shared__ float sgcn[NN][64];
    __shared__ float sh[NN][DD];
    __shared__ float sagg[NN][DD];
    __shared__ float sas[NN][HH], sad[NN][HH];
    __shared__ float se[32][HH];
    __shared__ float smx[NN][HH], sden[NN][HH];
    __shared__ float sAn[NN*NN];
    __shared__ int   ssrc[32], sdst[32];
    __shared__ float sred[4];

    const float* xp = x + (size_t)bt * NN * FF_IN;
    if (tid < NN*FF_IN) ((float*)sx)[tid] = xp[tid];
    if (tid < NN*NN) sAn[tid] = d_Anorm[tid];
    if (tid < E2) { ssrc[tid] = d_src2[tid]; sdst[tid] = d_dst2[tid]; }
    __syncthreads();

    // xw = x @ gcn_w + gcn_b   (5 x 64)
    for (int idx = tid; idx < NN*64; idx += 128) {
        int n = idx >> 6, c = idx & 63;
        float acc = gcn_b[c];
        #pragma unroll
        for (int f = 0; f < FF_IN; f++) acc += sx[n][f] * gcn_w[f*64 + c];
        sxw[n][c] = acc;
    }
    __syncthreads();

    // gcn = tanh(Anorm @ xw)
    for (int idx = tid; idx < NN*64; idx += 128) {
        int n = idx >> 6, c = idx & 63;
        float acc = 0.f;
        #pragma unroll
        for (int m = 0; m < NN; m++) acc += sAn[n*NN + m] * sxw[m][c];
        sgcn[n][c] = tanhf(acc);
    }
    __syncthreads();

    // h = gcn @ gat_w   (5 x 128)
    for (int idx = tid; idx < NN*DD; idx += 128) {
        int n = idx >> 7, d = idx & 127;
        float acc = 0.f;
        #pragma unroll 8
        for (int f = 0; f < 64; f++) acc += sgcn[n][f] * gat_w[f*DD + d];
        sh[n][d] = acc;
    }
    __syncthreads();

    // attention coefficients a_s, a_d (5 x 4 each)
    if (tid < NN*HH*2) {
        int n = tid / (HH*2), r = tid % (HH*2), hd = r >> 1, which = r & 1;
        const float* av = which ? a_dst : a_src;
        float acc = 0.f;
        #pragma unroll
        for (int c = 0; c < CC; c++) acc += sh[n][hd*CC + c] * av[hd*CC + c];
        if (which) sad[n][hd] = acc; else sas[n][hd] = acc;
    }
    __syncthreads();

    // edge scores + leaky relu
    for (int idx = tid; idx < E2*HH; idx += 128) {
        int e = idx >> 2, hd = idx & 3;
        float v = sas[ssrc[e]][hd] + sad[sdst[e]][hd];
        se[e][hd] = (v > 0.f) ? v : 0.2f * v;
    }
    __syncthreads();

    // per-dst softmax stats
    if (tid < NN*HH) {
        int n = tid >> 2, hd = tid & 3;
        float m = -1e30f;
        for (int e = 0; e < E2; e++) if (sdst[e] == n) m = fmaxf(m, se[e][hd]);
        float s = 0.f;
        for (int e = 0; e < E2; e++) if (sdst[e] == n) s += expf(se[e][hd] - m);
        smx[n][hd] = m; sden[n][hd] = s;
    }
    __syncthreads();

    // aggregate + gat bias
    for (int idx = tid; idx < NN*DD; idx += 128) {
        int n = idx >> 7, d = idx & 127;
        int hd = d >> 5;
        float m = smx[n][hd];
        float inv = 1.f / sden[n][hd];
        float acc = 0.f;
        for (int e = 0; e < E2; e++) {
            if (sdst[e] == n)
                acc += expf(se[e][hd] - m) * inv * sh[ssrc[e]][d];
        }
        sagg[n][d] = acc + gat_b[d];
    }

    // LN per node + mean over nodes + positional encoding
    int d = tid;
    float zacc = 0.f;
    for (int n = 0; n < NN; n++) {
        float v = sagg[n][d];
        float s1 = blockReduceSum128(v, sred);
        float mu = s1 * (1.f / DD);
        float dv = v - mu;
        float s2 = blockReduceSum128(dv*dv, sred);
        float var = s2 * (1.f / DD);
        zacc += dv * rsqrtf(var + 1e-5f) * gln_g[d] + gln_b[d];
    }
    zacc *= (1.f / NN);

    int t = bt % TT;
    float arg = (float)t * expf(-(float)((d >> 1) << 1) * (logf(10000.f) / (float)DD));
    zacc += (d & 1) ? cosf(arg) : sinf(arg);
    z[(size_t)bt * DD + d] = zacc;
}

// ---------------- SGEMM: C = A(MxK) @ B(KxN) + bias, optional ReLU ----------------
// 64x64 tile, K-step 16, 256 threads, 4x4 microtile.
template<int ACT>
__global__ void sgemm_bias(const float* __restrict__ A, const float* __restrict__ Bm,
                           const float* __restrict__ bias, float* __restrict__ Cm,
                           int M, int N, int K)
{
    __shared__ float As[16][65];
    __shared__ float Bs[16][68];
    int tid = threadIdx.x;
    int tx = tid & 15, ty = tid >> 4;
    int m0 = blockIdx.y * 64, n0 = blockIdx.x * 64;

    float acc[4][4];
    #pragma unroll
    for (int i = 0; i < 4; i++)
        #pragma unroll
        for (int j = 0; j < 4; j++) acc[i][j] = 0.f;

    for (int k0 = 0; k0 < K; k0 += 16) {
        #pragma unroll
        for (int l = 0; l < 4; l++) {
            int flat = tid + l*256;
            int ma = flat >> 4, ka = flat & 15;
            As[ka][ma] = A[(size_t)(m0 + ma)*K + k0 + ka];
            int kb = flat >> 6, nb = flat & 63;
            Bs[kb][nb] = Bm[(size_t)(k0 + kb)*N + n0 + nb];
        }
        __syncthreads();
        #pragma unroll
        for (int kk = 0; kk < 16; kk++) {
            float a[4], b[4];
            #pragma unroll
            for (int i = 0; i < 4; i++) a[i] = As[kk][ty*4 + i];
            #pragma unroll
            for (int j = 0; j < 4; j++) b[j] = Bs[kk][tx*4 + j];
            #pragma unroll
            for (int i = 0; i < 4; i++)
                #pragma unroll
                for (int j = 0; j < 4; j++)
                    acc[i][j] += a[i] * b[j];
        }
        __syncthreads();
    }

    #pragma unroll
    for (int i = 0; i < 4; i++) {
        int m = m0 + ty*4 + i;
        #pragma unroll
        for (int j = 0; j < 4; j++) {
            int n = n0 + tx*4 + j;
            float c = acc[i][j] + bias[n];
            if (ACT == 1) c = fmaxf(c, 0.f);
            Cm[(size_t)m*N + n] = c;
        }
    }
}

// ---------------- attention per (b, head) ----------------
__global__ void attn_kernel(const float* __restrict__ qkv, float* __restrict__ obuf)
{
    int b = blockIdx.x;
    int h = blockIdx.y;
    int tid = threadIdx.x;  // 128

    __shared__ float sq[TT*DHEAD], sk[TT*DHEAD], sv[TT*DHEAD];
    __shared__ float sS[TT*TT];

    const float* base = qkv + (size_t)b * TT * (3*DD);
    for (int idx = tid; idx < TT*DHEAD; idx += 128) {
        int t = idx >> 5, d = idx & 31;
        sq[idx] = base[t*(3*DD)          + h*DHEAD + d];
        sk[idx] = base[t*(3*DD) + DD     + h*DHEAD + d];
        sv[idx] = base[t*(3*DD) + 2*DD   + h*DHEAD + d];
    }
    __syncthreads();

    const float inv_scale = rsqrtf((float)DHEAD);
    for (int idx = tid; idx < TT*TT; idx += 128) {
        int i = idx / TT, j = idx % TT;
        float acc = 0.f;
        #pragma unroll
        for (int d = 0; d < DHEAD; d++) acc += sq[i*DHEAD + d] * sk[j*DHEAD + d];
        sS[idx] = acc * inv_scale;
    }
    __syncthreads();

    // rowwise softmax: warp per row
    int wid = tid >> 5, lane = tid & 31;
    for (int i = wid; i < TT; i += 4) {
        float m = -1e30f;
        for (int j = lane; j < TT; j += 32) m = fmaxf(m, sS[i*TT + j]);
        #pragma unroll
        for (int o = 16; o > 0; o >>= 1) m = fmaxf(m, __shfl_xor_sync(0xffffffffu, m, o));
        float s = 0.f;
        for (int j = lane; j < TT; j += 32) {
            float e = expf(sS[i*TT + j] - m);
            sS[i*TT + j] = e;
            s += e;
        }
        #pragma unroll
        for (int o = 16; o > 0; o >>= 1) s += __shfl_xor_sync(0xffffffffu, s, o);
        float inv = 1.f / s;
        for (int j = lane; j < TT; j += 32) sS[i*TT + j] *= inv;
    }
    __syncthreads();

    for (int idx = tid; idx < TT*DHEAD; idx += 128) {
        int i = idx >> 5, d = idx & 31;
        float acc = 0.f;
        #pragma unroll 8
        for (int j = 0; j < TT; j++) acc += sS[i*TT + j] * sv[j*DHEAD + d];
        obuf[((size_t)b*TT + i)*DD + h*DHEAD + d] = acc;
    }
}

// ---------------- residual + layernorm: z = LN(z + y)*g + b ----------------
__global__ void add_ln_kernel(float* __restrict__ z, const float* __restrict__ y,
                              const float* __restrict__ g, const float* __restrict__ b)
{
    int row = blockIdx.x;
    int d = threadIdx.x;  // 128
    __shared__ float sred[4];
    float v = z[(size_t)row*DD + d] + y[(size_t)row*DD + d];
    float s1 = blockReduceSum128(v, sred);
    float mu = s1 * (1.f / DD);
    float dv = v - mu;
    float s2 = blockReduceSum128(dv*dv, sred);
    float var = s2 * (1.f / DD);
    z[(size_t)row*DD + d] = dv * rsqrtf(var + 1e-5f) * g[d] + b[d];
}

// ---------------- 6 MLP heads on last timestep ----------------
__global__ void heads_kernel(const float* __restrict__ z,
                             const float* __restrict__ hw1, const float* __restrict__ hb1,
                             const float* __restrict__ hw2, const float* __restrict__ hb2,
                             float* __restrict__ out)
{
    int b = blockIdx.x;
    int k = blockIdx.y;
    int tid = threadIdx.x;  // 64
    __shared__ float slast[DD];
    __shared__ float sh1[64];
    const float* zr = z + ((size_t)b*TT + (TT-1))*DD;
    slast[tid] = zr[tid];
    slast[tid + 64] = zr[tid + 64];
    __syncthreads();

    float acc = hb1[k*64 + tid];
    const float* w1 = hw1 + (size_t)k*DD*64;
    #pragma unroll 8
    for (int d = 0; d < DD; d++) acc += slast[d] * w1[d*64 + tid];
    sh1[tid] = fmaxf(acc, 0.f);
    __syncthreads();

    if (tid < 5) {
        float a2 = hb2[k*5 + tid];
        const float* w2 = hw2 + (size_t)k*64*5;
        #pragma unroll 8
        for (int m = 0; m < 64; m++) a2 += sh1[m] * w2[m*5 + tid];
        out[((size_t)k*BB + b)*5 + tid] = a2;
    }
}

// ---------------- launcher ----------------
extern "C" void kernel_launch(void* const* d_in, const int* in_sizes, int n_in,
                              void* d_out, int out_size)
{
    const float* x        = (const float*)d_in[0];
    const int*   ei       = (const int*)  d_in[1];
    const float* gcn_w    = (const float*)d_in[2];
    const float* gcn_b    = (const float*)d_in[3];
    const float* gat_w    = (const float*)d_in[4];
    const float* gat_a_s  = (const float*)d_in[5];
    const float* gat_a_d  = (const float*)d_in[6];
    const float* gat_b    = (const float*)d_in[7];
    const float* gln_g    = (const float*)d_in[8];
    const float* gln_b    = (const float*)d_in[9];
    const float* tw_qkv   = (const float*)d_in[10];
    const float* tb_qkv   = (const float*)d_in[11];
    const float* tw_o     = (const float*)d_in[12];
    const float* tb_o     = (const float*)d_in[13];
    const float* ln1_g    = (const float*)d_in[14];
    const float* ln1_b    = (const float*)d_in[15];
    const float* w_ff1    = (const float*)d_in[16];
    const float* b_ff1    = (const float*)d_in[17];
    const float* w_ff2    = (const float*)d_in[18];
    const float* b_ff2    = (const float*)d_in[19];
    const float* ln2_g    = (const float*)d_in[20];
    const float* ln2_b    = (const float*)d_in[21];
    const float* hw1      = (const float*)d_in[22];
    const float* hb1      = (const float*)d_in[23];
    const float* hw2      = (const float*)d_in[24];
    const float* hb2      = (const float*)d_in[25];
    float* out = (float*)d_out;

    float *zp, *qkvp, *op, *ffp, *tmpp;
    cudaGetSymbolAddress((void**)&zp,   d_z);
    cudaGetSymbolAddress((void**)&qkvp, d_qkv);
    cudaGetSymbolAddress((void**)&op,   d_o);
    cudaGetSymbolAddress((void**)&ffp,  d_ff);
    cudaGetSymbolAddress((void**)&tmpp, d_tmp);

    int E = in_sizes[1] / 2;

    build_graph_kernel<<<1, 32>>>(ei, E);

    gcn_gat_kernel<<<BT, 128>>>(x, gcn_w, gcn_b, gat_w, gat_a_s, gat_a_d,
                                gat_b, gln_g, gln_b, zp, E + NN);

    for (int i = 0; i < 3; i++) {
        // qkv = z @ Wqkv + b      (18432 x 384)
        sgemm_bias<0><<<dim3((3*DD)/64, BT/64), 256>>>(
            zp, tw_qkv + (size_t)i*DD*3*DD, tb_qkv + (size_t)i*3*DD, qkvp, BT, 3*DD, DD);
        // attention
        attn_kernel<<<dim3(BB, NHEAD), 128>>>(qkvp, op);
        // o @ Wo + b
        sgemm_bias<0><<<dim3(DD/64, BT/64), 256>>>(
            op, tw_o + (size_t)i*DD*DD, tb_o + (size_t)i*DD, tmpp, BT, DD, DD);
        // z = LN(z + oproj)
        add_ln_kernel<<<BT, 128>>>(zp, tmpp, ln1_g + (size_t)i*DD, ln1_b + (size_t)i*DD);
        // ff1 = relu(z @ W1 + b1)
        sgemm_bias<1><<<dim3(FFD/64, BT/64), 256>>>(
            zp, w_ff1 + (size_t)i*DD*FFD, b_ff1 + (size_t)i*FFD, ffp, BT, FFD, DD);
        // ff2 = ff1 @ W2 + b2
        sgemm_bias<0><<<dim3(DD/64, BT/64), 256>>>(
            ffp, w_ff2 + (size_t)i*FFD*DD, b_ff2 + (size_t)i*DD, tmpp, BT, DD, FFD);
        // z = LN(z + ff2)
        add_ln_kernel<<<BT, 128>>>(zp, tmpp, ln2_g + (size_t)i*DD, ln2_b + (size_t)i*DD);
    }

    heads_kernel<<<dim3(BB, 6), 64>>>(zp, hw1, hb1, hw2, hb2, out);
}

// round 2
// speedup vs baseline: 1.4765x; 1.4765x over previous
#include <cuda_runtime.h>
#include <math.h>

// Problem constants (fixed by reference)
#define BB 256
#define TT 72
#define NN 5
#define FF_IN 10
#define HH 4
#define CC 32
#define DD 128
#define FFD 256
#define NHEAD 4
#define DHEAD 32
#define BT (BB*TT)   // 18432

// ---------------- device scratch (no allocations allowed) ----------------
__device__ float d_z[BT*DD];
__device__ float d_qkv[BT*3*DD];
__device__ float d_o[BT*DD];
__device__ float d_ff[BT*FFD];
__device__ float d_tmp[BT*DD];
__device__ float d_Anorm[NN*NN];
__device__ int   d_src2[64];
__device__ int   d_dst2[64];

// ---------------- f32x2 packed helpers ----------------
__device__ __forceinline__ unsigned long long pk2(float x, float y) {
    unsigned long long r;
    asm("mov.b64 %0, {%1, %2};" : "=l"(r) : "f"(x), "f"(y));
    return r;
}
__device__ __forceinline__ void fma2(unsigned long long &acc, unsigned long long a, unsigned long long b) {
    asm("fma.rn.f32x2 %0, %1, %2, %0;" : "+l"(acc) : "l"(a), "l"(b));
}
__device__ __forceinline__ void upk2(unsigned long long v, float &x, float &y) {
    asm("mov.b64 {%0, %1}, %2;" : "=f"(x), "=f"(y) : "l"(v));
}

// ---------------- graph build (single thread, trivial) ----------------
__global__ void build_graph_kernel(const int* __restrict__ ei, int E) {
    if (threadIdx.x != 0 || blockIdx.x != 0) return;
    float A[NN][NN];
    for (int i = 0; i < NN*NN; i++) ((float*)A)[i] = 0.f;
    for (int e = 0; e < E; e++) {
        int s = ei[e];
        int d = ei[E + e];
        A[d][s] += 1.f;
        d_src2[e] = s; d_dst2[e] = d;
    }
    for (int n = 0; n < NN; n++) {
        A[n][n] += 1.f;
        d_src2[E + n] = n; d_dst2[E + n] = n;
    }
    float dinv[NN];
    for (int n = 0; n < NN; n++) {
        float s = 0.f;
        for (int j = 0; j < NN; j++) s += A[n][j];
        dinv[n] = (s > 0.f) ? (1.f / sqrtf(s)) : 0.f;
    }
    for (int i = 0; i < NN; i++)
        for (int j = 0; j < NN; j++)
            d_Anorm[i*NN + j] = dinv[i] * A[i][j] * dinv[j];
}

// ---------------- block reduce (128 threads) ----------------
__device__ __forceinline__ float blockReduceSum128(float v, float* sred) {
    __syncthreads();
    #pragma unroll
    for (int o = 16; o > 0; o >>= 1) v += __shfl_xor_sync(0xffffffffu, v, o);
    if ((threadIdx.x & 31) == 0) sred[threadIdx.x >> 5] = v;
    __syncthreads();
    return sred[0] + sred[1] + sred[2] + sred[3];
}

// ---------------- fused GCN + GAT + LN + node-mean + PE ----------------
__global__ void gcn_gat_kernel(
    const float* __restrict__ x,
    const float* __restrict__ gcn_w, const float* __restrict__ gcn_b,
    const float* __restrict__ gat_w, const float* __restrict__ a_src,
    const float* __restrict__ a_dst, const float* __restrict__ gat_b,
    const float* __restrict__ gln_g, const float* __restrict__ gln_b,
    float* __restrict__ z, int E2)
{
    int bt = blockIdx.x;
    int tid = threadIdx.x;  // 128

    __shared__ float sx[NN][FF_IN];
    __shared__ float sxw[NN][64];
    __shared__ float sgcn[NN][64];
    __shared__ float sh[NN][DD];
    __shared__ float sagg[NN][DD];
    __shared__ float sas[NN][HH], sad[NN][HH];
    __shared__ float se[32][HH];
    __shared__ float smx[NN][HH], sden[NN][HH];
    __shared__ float sAn[NN*NN];
    __shared__ int   ssrc[32], sdst[32];
    __shared__ float sred[4];

    const float* xp = x + (size_t)bt * NN * FF_IN;
    if (tid < NN*FF_IN) ((float*)sx)[tid] = xp[tid];
    if (tid < NN*NN) sAn[tid] = d_Anorm[tid];
    if (tid < E2) { ssrc[tid] = d_src2[tid]; sdst[tid] = d_dst2[tid]; }
    __syncthreads();

    // xw = x @ gcn_w + gcn_b   (5 x 64)
    for (int idx = tid; idx < NN*64; idx += 128) {
        int n = idx >> 6, c = idx & 63;
        float acc = gcn_b[c];
        #pragma unroll
        for (int f = 0; f < FF_IN; f++) acc += sx[n][f] * gcn_w[f*64 + c];
        sxw[n][c] = acc;
    }
    __syncthreads();

    // gcn = tanh(Anorm @ xw)
    for (int idx = tid; idx < NN*64; idx += 128) {
        int n = idx >> 6, c = idx & 63;
        float acc = 0.f;
        #pragma unroll
        for (int m = 0; m < NN; m++) acc += sAn[n*NN + m] * sxw[m][c];
        sgcn[n][c] = tanhf(acc);
    }
    __syncthreads();

    // h = gcn @ gat_w   (5 x 128)
    for (int idx = tid; idx < NN*DD; idx += 128) {
        int n = idx >> 7, d = idx & 127;
        float acc = 0.f;
        #pragma unroll 8
        for (int f = 0; f < 64; f++) acc += sgcn[n][f] * gat_w[f*DD + d];
        sh[n][d] = acc;
    }
    __syncthreads();

    // attention coefficients a_s, a_d (5 x 4 each)
    if (tid < NN*HH*2) {
        int n = tid / (HH*2), r = tid % (HH*2), hd = r >> 1, which = r & 1;
        const float* av = which ? a_dst : a_src;
        float acc = 0.f;
        #pragma unroll
        for (int c = 0; c < CC; c++) acc += sh[n][hd*CC + c] * av[hd*CC + c];
        if (which) sad[n][hd] = acc; else sas[n][hd] = acc;
    }
    __syncthreads();

    // edge scores + leaky relu
    for (int idx = tid; idx < E2*HH; idx += 128) {
        int e = idx >> 2, hd = idx & 3;
        float v = sas[ssrc[e]][hd] + sad[sdst[e]][hd];
        se[e][hd] = (v > 0.f) ? v : 0.2f * v;
    }
    __syncthreads();

    // per-dst softmax stats
    if (tid < NN*HH) {
        int n = tid >> 2, hd = tid & 3;
        float m = -1e30f;
        for (int e = 0; e < E2; e++) if (sdst[e] == n) m = fmaxf(m, se[e][hd]);
        float s = 0.f;
        for (int e = 0; e < E2; e++) if (sdst[e] == n) s += expf(se[e][hd] - m);
        smx[n][hd] = m; sden[n][hd] = s;
    }
    __syncthreads();

    // aggregate + gat bias
    for (int idx = tid; idx < NN*DD; idx += 128) {
        int n = idx >> 7, d = idx & 127;
        int hd = d >> 5;
        float m = smx[n][hd];
        float inv = 1.f / sden[n][hd];
        float acc = 0.f;
        for (int e = 0; e < E2; e++) {
            if (sdst[e] == n)
                acc += expf(se[e][hd] - m) * inv * sh[ssrc[e]][d];
        }
        sagg[n][d] = acc + gat_b[d];
    }

    // LN per node + mean over nodes + positional encoding
    int d = tid;
    float zacc = 0.f;
    for (int n = 0; n < NN; n++) {
        float v = sagg[n][d];
        float s1 = blockReduceSum128(v, sred);
        float mu = s1 * (1.f / DD);
        float dv = v - mu;
        float s2 = blockReduceSum128(dv*dv, sred);
        float var = s2 * (1.f / DD);
        zacc += dv * rsqrtf(var + 1e-5f) * gln_g[d] + gln_b[d];
    }
    zacc *= (1.f / NN);

    int t = bt % TT;
    float arg = (float)t * expf(-(float)((d >> 1) << 1) * (logf(10000.f) / (float)DD));
    zacc += (d & 1) ? cosf(arg) : sinf(arg);
    z[(size_t)bt * DD + d] = zacc;
}

// ---------------- SGEMM with f32x2: C = A(MxK) @ B(KxN) + bias, optional ReLU ----
// 128x128 tile, K-step 16, 256 threads, 8x8 microtile, acc packed in pairs along M.
template<int ACT>
__global__ void __launch_bounds__(256, 2)
sgemm_f32x2(const float* __restrict__ A, const float* __restrict__ Bm,
            const float* __restrict__ bias, float* __restrict__ Cm,
            int M, int N, int K)
{
    __shared__ float As[16][132];   // [k][m], padded
    __shared__ float Bs[16][132];   // [k][n], padded
    int tid = threadIdx.x;
    int tx = tid & 15, ty = tid >> 4;
    int m0 = blockIdx.y * 128, n0 = blockIdx.x * 128;

    unsigned long long acc[4][8];   // 4 m-pairs x 8 n
    #pragma unroll
    for (int i = 0; i < 4; i++)
        #pragma unroll
        for (int j = 0; j < 8; j++) acc[i][j] = 0ULL;  // (0.f, 0.f)

    for (int k0 = 0; k0 < K; k0 += 16) {
        // Load A tile (transpose into As[k][m]); 512 float4s, 2 per thread
        #pragma unroll
        for (int l = 0; l < 2; l++) {
            int f = tid + l*256;          // 0..511
            int ma = f >> 2, kc = f & 3;  // m 0..127, k-chunk 0..3
            float4 v = *(const float4*)&A[(size_t)(m0 + ma)*K + k0 + kc*4];
            As[kc*4 + 0][ma] = v.x;
            As[kc*4 + 1][ma] = v.y;
            As[kc*4 + 2][ma] = v.z;
            As[kc*4 + 3][ma] = v.w;
        }
        // Load B tile directly
        #pragma unroll
        for (int l = 0; l < 2; l++) {
            int f = tid + l*256;           // 0..511
            int kb = f >> 5, nc = f & 31;  // k 0..15, n-chunk 0..31
            float4 v = *(const float4*)&Bm[(size_t)(k0 + kb)*N + n0 + nc*4];
            *(float4*)&Bs[kb][nc*4] = v;
        }
        __syncthreads();

        #pragma unroll
        for (int kk = 0; kk < 16; kk++) {
            float4 a0 = *(const float4*)&As[kk][ty*8];
            float4 a1 = *(const float4*)&As[kk][ty*8 + 4];
            float4 b0 = *(const float4*)&Bs[kk][tx*8];
            float4 b1 = *(const float4*)&Bs[kk][tx*8 + 4];
            unsigned long long a2[4];
            a2[0] = pk2(a0.x, a0.y);
            a2[1] = pk2(a0.z, a0.w);
            a2[2] = pk2(a1.x, a1.y);
            a2[3] = pk2(a1.z, a1.w);
            float bv[8] = {b0.x, b0.y, b0.z, b0.w, b1.x, b1.y, b1.z, b1.w};
            #pragma unroll
            for (int j = 0; j < 8; j++) {
                unsigned long long b2 = pk2(bv[j], bv[j]);
                #pragma unroll
                for (int i = 0; i < 4; i++) fma2(acc[i][j], a2[i], b2);
            }
        }
        __syncthreads();
    }

    // Epilogue: bias (+ relu), write 8 rows x 8 cols per thread
    float bsv[8];
    #pragma unroll
    for (int j = 0; j < 8; j++) bsv[j] = bias[n0 + tx*8 + j];

    #pragma unroll
    for (int i = 0; i < 4; i++) {
        float r0[8], r1[8];
        #pragma unroll
        for (int j = 0; j < 8; j++) {
            float lo, hi;
            upk2(acc[i][j], lo, hi);
            float c0 = lo + bsv[j];
            float c1 = hi + bsv[j];
            if (ACT == 1) { c0 = fmaxf(c0, 0.f); c1 = fmaxf(c1, 0.f); }
            r0[j] = c0; r1[j] = c1;
        }
        int m = m0 + ty*8 + i*2;
        float* p0 = &Cm[(size_t)m*N + n0 + tx*8];
        float* p1 = &Cm[(size_t)(m+1)*N + n0 + tx*8];
        *(float4*)p0       = make_float4(r0[0], r0[1], r0[2], r0[3]);
        *(float4*)(p0 + 4) = make_float4(r0[4], r0[5], r0[6], r0[7]);
        *(float4*)p1       = make_float4(r1[0], r1[1], r1[2], r1[3]);
        *(float4*)(p1 + 4) = make_float4(r1[4], r1[5], r1[6], r1[7]);
    }
}

// ---------------- attention per (b, head), conflict-free & register-tiled ------
#define QKS 36   // row stride for q/k/v tiles (float4-aligned, conflict-free)
#define SSS 76   // row stride for S (float4-aligned)
__global__ void attn_kernel(const float* __restrict__ qkv, float* __restrict__ obuf)
{
    int b = blockIdx.x;
    int h = blockIdx.y;
    int tid = threadIdx.x;  // 128

    __shared__ float sq[TT*QKS];    // Q, then reused implicitly (dead after S)
    __shared__ float skv[TT*QKS];   // K during S, then reloaded with V
    __shared__ float sS[TT*SSS];

    const float* base = qkv + (size_t)b * TT * (3*DD) + h*DHEAD;
    // load Q and K
    for (int idx = tid; idx < TT*DHEAD; idx += 128) {
        int t = idx >> 5, d = idx & 31;
        sq[t*QKS + d]  = base[t*(3*DD)      + d];
        skv[t*QKS + d] = base[t*(3*DD) + DD + d];
    }
    __syncthreads();

    const float inv_scale = rsqrtf((float)DHEAD);
    // S = Q @ K^T * inv_scale : 4x4 register tiles, 18x18 = 324 tiles
    for (int tt = tid; tt < 324; tt += 128) {
        int i0 = (tt / 18) * 4, j0 = (tt % 18) * 4;
        float acc[4][4];
        #pragma unroll
        for (int a = 0; a < 4; a++)
            #pragma unroll
            for (int c = 0; c < 4; c++) acc[a][c] = 0.f;
        #pragma unroll
        for (int d4 = 0; d4 < DHEAD; d4 += 4) {
            float4 q[4], k[4];
            #pragma unroll
            for (int a = 0; a < 4; a++) q[a] = *(const float4*)&sq[(i0+a)*QKS + d4];
            #pragma unroll
            for (int c = 0; c < 4; c++) k[c] = *(const float4*)&skv[(j0+c)*QKS + d4];
            #pragma unroll
            for (int a = 0; a < 4; a++)
                #pragma unroll
                for (int c = 0; c < 4; c++)
                    acc[a][c] += q[a].x*k[c].x + q[a].y*k[c].y + q[a].z*k[c].z + q[a].w*k[c].w;
        }
        #pragma unroll
        for (int a = 0; a < 4; a++)
            #pragma unroll
            for (int c = 0; c < 4; c++)
                sS[(i0+a)*SSS + j0 + c] = acc[a][c] * inv_scale;
    }
    __syncthreads();

    // rowwise softmax: warp per row
    int wid = tid >> 5, lane = tid & 31;
    for (int i = wid; i < TT; i += 4) {
        float m = -1e30f;
        for (int j = lane; j < TT; j += 32) m = fmaxf(m, sS[i*SSS + j]);
        #pragma unroll
        for (int o = 16; o > 0; o >>= 1) m = fmaxf(m, __shfl_xor_sync(0xffffffffu, m, o));
        float s = 0.f;
        for (int j = lane; j < TT; j += 32) {
            float e = expf(sS[i*SSS + j] - m);
            sS[i*SSS + j] = e;
            s += e;
        }
        #pragma unroll
        for (int o = 16; o > 0; o >>= 1) s += __shfl_xor_sync(0xffffffffu, s, o);
        float inv = 1.f / s;
        for (int j = lane; j < TT; j += 32) sS[i*SSS + j] *= inv;
    }
    __syncthreads();

    // load V into skv (K is dead now)
    for (int idx = tid; idx < TT*DHEAD; idx += 128) {
        int t = idx >> 5, d = idx & 31;
        skv[t*QKS + d] = base[t*(3*DD) + 2*DD + d];
    }
    __syncthreads();

    // O = S @ V : tiles of (2 rows x 8 d), 36 x 4 = 144 tiles
    for (int tt = tid; tt < 144; tt += 128) {
        int i0 = (tt >> 2) * 2;
        int d0 = (tt & 3) * 8;
        float acc0[8], acc1[8];
        #pragma unroll
        for (int c = 0; c < 8; c++) { acc0[c] = 0.f; acc1[c] = 0.f; }
        for (int j = 0; j < TT; j++) {
            float s0 = sS[i0*SSS + j];
            float s1 = sS[(i0+1)*SSS + j];
            float4 v0 = *(const float4*)&skv[j*QKS + d0];
            float4 v1 = *(const float4*)&skv[j*QKS + d0 + 4];
            acc0[0] += s0*v0.x; acc0[1] += s0*v0.y; acc0[2] += s0*v0.z; acc0[3] += s0*v0.w;
            acc0[4] += s0*v1.x; acc0[5] += s0*v1.y; acc0[6] += s0*v1.z; acc0[7] += s0*v1.w;
            acc1[0] += s1*v0.x; acc1[1] += s1*v0.y; acc1[2] += s1*v0.z; acc1[3] += s1*v0.w;
            acc1[4] += s1*v1.x; acc1[5] += s1*v1.y; acc1[6] += s1*v1.z; acc1[7] += s1*v1.w;
        }
        float* o0 = &obuf[((size_t)b*TT + i0)*DD + h*DHEAD + d0];
        float* o1 = o0 + DD;
        *(float4*)o0       = make_float4(acc0[0], acc0[1], acc0[2], acc0[3]);
        *(float4*)(o0 + 4) = make_float4(acc0[4], acc0[5], acc0[6], acc0[7]);
        *(float4*)o1       = make_float4(acc1[0], acc1[1], acc1[2], acc1[3]);
        *(float4*)(o1 + 4) = make_float4(acc1[4], acc1[5], acc1[6], acc1[7]);
    }
}

// ---------------- residual + layernorm: z = LN(z + y)*g + b ----------------
__global__ void add_ln_kernel(float* __restrict__ z, const float* __restrict__ y,
                              const float* __restrict__ g, const float* __restrict__ b)
{
    int row = blockIdx.x;
    int d = threadIdx.x;  // 128
    __shared__ float sred[4];
    float v = z[(size_t)row*DD + d] + y[(size_t)row*DD + d];
    float s1 = blockReduceSum128(v, sred);
    float mu = s1 * (1.f / DD);
    float dv = v - mu;
    float s2 = blockReduceSum128(dv*dv, sred);
    float var = s2 * (1.f / DD);
    z[(size_t)row*DD + d] = dv * rsqrtf(var + 1e-5f) * g[d] + b[d];
}

// ---------------- 6 MLP heads on last timestep ----------------
__global__ void heads_kernel(const float* __restrict__ z,
                             const float* __restrict__ hw1, const float* __restrict__ hb1,
                             const float* __restrict__ hw2, const float* __restrict__ hb2,
                             float* __restrict__ out)
{
    int b = blockIdx.x;
    int k = blockIdx.y;
    int tid = threadIdx.x;  // 64
    __shared__ float slast[DD];
    __shared__ float sh1[64];
    const float* zr = z + ((size_t)b*TT + (TT-1))*DD;
    slast[tid] = zr[tid];
    slast[tid + 64] = zr[tid + 64];
    __syncthreads();

    float acc = hb1[k*64 + tid];
    const float* w1 = hw1 + (size_t)k*DD*64;
    #pragma unroll 8
    for (int d = 0; d < DD; d++) acc += slast[d] * w1[d*64 + tid];
    sh1[tid] = fmaxf(acc, 0.f);
    __syncthreads();

    if (tid < 5) {
        float a2 = hb2[k*5 + tid];
        const float* w2 = hw2 + (size_t)k*64*5;
        #pragma unroll 8
        for (int m = 0; m < 64; m++) a2 += sh1[m] * w2[m*5 + tid];
        out[((size_t)k*BB + b)*5 + tid] = a2;
    }
}

// ---------------- launcher ----------------
extern "C" void kernel_launch(void* const* d_in, const int* in_sizes, int n_in,
                              void* d_out, int out_size)
{
    const float* x        = (const float*)d_in[0];
    const int*   ei       = (const int*)  d_in[1];
    const float* gcn_w    = (const float*)d_in[2];
    const float* gcn_b    = (const float*)d_in[3];
    const float* gat_w    = (const float*)d_in[4];
    const float* gat_a_s  = (const float*)d_in[5];
    const float* gat_a_d  = (const float*)d_in[6];
    const float* gat_b    = (const float*)d_in[7];
    const float* gln_g    = (const float*)d_in[8];
    const float* gln_b    = (const float*)d_in[9];
    const float* tw_qkv   = (const float*)d_in[10];
    const float* tb_qkv   = (const float*)d_in[11];
    const float* tw_o     = (const float*)d_in[12];
    const float* tb_o     = (const float*)d_in[13];
    const float* ln1_g    = (const float*)d_in[14];
    const float* ln1_b    = (const float*)d_in[15];
    const float* w_ff1    = (const float*)d_in[16];
    const float* b_ff1    = (const float*)d_in[17];
    const float* w_ff2    = (const float*)d_in[18];
    const float* b_ff2    = (const float*)d_in[19];
    const float* ln2_g    = (const float*)d_in[20];
    const float* ln2_b    = (const float*)d_in[21];
    const float* hw1      = (const float*)d_in[22];
    const float* hb1      = (const float*)d_in[23];
    const float* hw2      = (const float*)d_in[24];
    const float* hb2      = (const float*)d_in[25];
    float* out = (float*)d_out;

    float *zp, *qkvp, *op, *ffp, *tmpp;
    cudaGetSymbolAddress((void**)&zp,   d_z);
    cudaGetSymbolAddress((void**)&qkvp, d_qkv);
    cudaGetSymbolAddress((void**)&op,   d_o);
    cudaGetSymbolAddress((void**)&ffp,  d_ff);
    cudaGetSymbolAddress((void**)&tmpp, d_tmp);

    int E = in_sizes[1] / 2;

    build_graph_kernel<<<1, 32>>>(ei, E);

    gcn_gat_kernel<<<BT, 128>>>(x, gcn_w, gcn_b, gat_w, gat_a_s, gat_a_d,
                                gat_b, gln_g, gln_b, zp, E + NN);

    for (int i = 0; i < 3; i++) {
        // qkv = z @ Wqkv + b      (18432 x 384)
        sgemm_f32x2<0><<<dim3((3*DD)/128, BT/128), 256>>>(
            zp, tw_qkv + (size_t)i*DD*3*DD, tb_qkv + (size_t)i*3*DD, qkvp, BT, 3*DD, DD);
        // attention
        attn_kernel<<<dim3(BB, NHEAD), 128>>>(qkvp, op);
        // o @ Wo + b
        sgemm_f32x2<0><<<dim3(DD/128, BT/128), 256>>>(
            op, tw_o + (size_t)i*DD*DD, tb_o + (size_t)i*DD, tmpp, BT, DD, DD);
        // z = LN(z + oproj)
        add_ln_kernel<<<BT, 128>>>(zp, tmpp, ln1_g + (size_t)i*DD, ln1_b + (size_t)i*DD);
        // ff1 = relu(z @ W1 + b1)
        sgemm_f32x2<1><<<dim3(FFD/128, BT/128), 256>>>(
            zp, w_ff1 + (size_t)i*DD*FFD, b_ff1 + (size_t)i*FFD, ffp, BT, FFD, DD);
        // ff2 = ff1 @ W2 + b2
        sgemm_f32x2<0><<<dim3(DD/128, BT/128), 256>>>(
            ffp, w_ff2 + (size_t)i*FFD*DD, b_ff2 + (size_t)i*DD, tmpp, BT, DD, FFD);
        // z = LN(z + ff2)
        add_ln_kernel<<<BT, 128>>>(zp, tmpp, ln2_g + (size_t)i*DD, ln2_b + (size_t)i*DD);
    }

    heads_kernel<<<dim3(BB, 6), 64>>>(zp, hw1, hb1, hw2, hb2, out);
}

// round 3
// speedup vs baseline: 1.5782x; 1.0689x over previous
#include <cuda_runtime.h>
#include <math.h>

// Problem constants (fixed by reference)
#define BB 256
#define TT 72
#define NN 5
#define FF_IN 10
#define HH 4
#define CC 32
#define DD 128
#define FFD 256
#define NHEAD 4
#define DHEAD 32
#define BT (BB*TT)   // 18432

// ---------------- device scratch (no allocations allowed) ----------------
__device__ float d_z[BT*DD];
__device__ float d_qkv[BT*3*DD];
__device__ float d_o[BT*DD];
__device__ float d_ff[BT*FFD];
__device__ float d_Anorm[NN*NN];
__device__ int   d_src2[64];
__device__ int   d_dst2[64];

// ---------------- f32x2 packed helpers ----------------
__device__ __forceinline__ unsigned long long pk2(float x, float y) {
    unsigned long long r;
    asm("mov.b64 %0, {%1, %2};" : "=l"(r) : "f"(x), "f"(y));
    return r;
}
__device__ __forceinline__ void fma2(unsigned long long &acc, unsigned long long a, unsigned long long b) {
    asm("fma.rn.f32x2 %0, %1, %2, %0;" : "+l"(acc) : "l"(a), "l"(b));
}
__device__ __forceinline__ void upk2(unsigned long long v, float &x, float &y) {
    asm("mov.b64 {%0, %1}, %2;" : "=f"(x), "=f"(y) : "l"(v));
}

// ---------------- graph build (single thread, trivial) ----------------
__global__ void build_graph_kernel(const int* __restrict__ ei, int E) {
    if (threadIdx.x != 0 || blockIdx.x != 0) return;
    float A[NN][NN];
    for (int i = 0; i < NN*NN; i++) ((float*)A)[i] = 0.f;
    for (int e = 0; e < E; e++) {
        int s = ei[e];
        int d = ei[E + e];
        A[d][s] += 1.f;
        d_src2[e] = s; d_dst2[e] = d;
    }
    for (int n = 0; n < NN; n++) {
        A[n][n] += 1.f;
        d_src2[E + n] = n; d_dst2[E + n] = n;
    }
    float dinv[NN];
    for (int n = 0; n < NN; n++) {
        float s = 0.f;
        for (int j = 0; j < NN; j++) s += A[n][j];
        dinv[n] = (s > 0.f) ? (1.f / sqrtf(s)) : 0.f;
    }
    for (int i = 0; i < NN; i++)
        for (int j = 0; j < NN; j++)
            d_Anorm[i*NN + j] = dinv[i] * A[i][j] * dinv[j];
}

// ---------------- fused dual block reduce (128 threads) ----------------
__device__ __forceinline__ void blockReduceSum2_128(float &a, float &b, float* sred) {
    __syncthreads();
    #pragma unroll
    for (int o = 16; o > 0; o >>= 1) {
        a += __shfl_xor_sync(0xffffffffu, a, o);
        b += __shfl_xor_sync(0xffffffffu, b, o);
    }
    if ((threadIdx.x & 31) == 0) {
        int w = threadIdx.x >> 5;
        sred[w] = a; sred[4 + w] = b;
    }
    __syncthreads();
    a = sred[0] + sred[1] + sred[2] + sred[3];
    b = sred[4] + sred[5] + sred[6] + sred[7];
}

// ---------------- fused GCN + GAT + LN + node-mean + PE ----------------
__global__ void gcn_gat_kernel(
    const float* __restrict__ x,
    const float* __restrict__ gcn_w, const float* __restrict__ gcn_b,
    const float* __restrict__ gat_w, const float* __restrict__ a_src,
    const float* __restrict__ a_dst, const float* __restrict__ gat_b,
    const float* __restrict__ gln_g, const float* __restrict__ gln_b,
    float* __restrict__ z, int E2)
{
    int bt = blockIdx.x;
    int tid = threadIdx.x;  // 128

    __shared__ float sx[NN][FF_IN];
    __shared__ float sxw[NN][64];
    __shared__ float sgcn[NN][64];
    __shared__ float sh[NN][DD];
    __shared__ float sagg[NN][DD];
    __shared__ float sas[NN][HH], sad[NN][HH];
    __shared__ float se[32][HH];
    __shared__ float salpha[32][HH];
    __shared__ float smx[NN][HH], sden[NN][HH];
    __shared__ float sAn[NN*NN];
    __shared__ int   ssrc[32], sdst[32];
    __shared__ float sred[8];

    const float* xp = x + (size_t)bt * NN * FF_IN;
    if (tid < NN*FF_IN) ((float*)sx)[tid] = xp[tid];
    if (tid < NN*NN) sAn[tid] = d_Anorm[tid];
    if (tid < E2) { ssrc[tid] = d_src2[tid]; sdst[tid] = d_dst2[tid]; }
    __syncthreads();

    // xw = x @ gcn_w + gcn_b   (5 x 64)
    for (int idx = tid; idx < NN*64; idx += 128) {
        int n = idx >> 6, c = idx & 63;
        float acc = gcn_b[c];
        #pragma unroll
        for (int f = 0; f < FF_IN; f++) acc += sx[n][f] * gcn_w[f*64 + c];
        sxw[n][c] = acc;
    }
    __syncthreads();

    // gcn = tanh(Anorm @ xw)
    for (int idx = tid; idx < NN*64; idx += 128) {
        int n = idx >> 6, c = idx & 63;
        float acc = 0.f;
        #pragma unroll
        for (int m = 0; m < NN; m++) acc += sAn[n*NN + m] * sxw[m][c];
        sgcn[n][c] = tanhf(acc);
    }
    __syncthreads();

    // h = gcn @ gat_w   (5 x 128)
    for (int idx = tid; idx < NN*DD; idx += 128) {
        int n = idx >> 7, d = idx & 127;
        float acc = 0.f;
        #pragma unroll 8
        for (int f = 0; f < 64; f++) acc += sgcn[n][f] * gat_w[f*DD + d];
        sh[n][d] = acc;
    }
    __syncthreads();

    // attention coefficients a_s, a_d (5 x 4 each)
    if (tid < NN*HH*2) {
        int n = tid / (HH*2), r = tid % (HH*2), hd = r >> 1, which = r & 1;
        const float* av = which ? a_dst : a_src;
        float acc = 0.f;
        #pragma unroll
        for (int c = 0; c < CC; c++) acc += sh[n][hd*CC + c] * av[hd*CC + c];
        if (which) sad[n][hd] = acc; else sas[n][hd] = acc;
    }
    __syncthreads();

    // edge scores + leaky relu
    for (int idx = tid; idx < E2*HH; idx += 128) {
        int e = idx >> 2, hd = idx & 3;
        float v = sas[ssrc[e]][hd] + sad[sdst[e]][hd];
        se[e][hd] = (v > 0.f) ? v : 0.2f * v;
    }
    __syncthreads();

    // per-dst softmax stats
    if (tid < NN*HH) {
        int n = tid >> 2, hd = tid & 3;
        float m = -1e30f;
        for (int e = 0; e < E2; e++) if (sdst[e] == n) m = fmaxf(m, se[e][hd]);
        float s = 0.f;
        for (int e = 0; e < E2; e++) if (sdst[e] == n) s += __expf(se[e][hd] - m);
        smx[n][hd] = m; sden[n][hd] = s;
    }
    __syncthreads();

    // alpha = exp(e - m[dst]) / den[dst]  (precomputed ONCE per edge/head)
    for (int idx = tid; idx < E2*HH; idx += 128) {
        int e = idx >> 2, hd = idx & 3;
        int n = sdst[e];
        salpha[e][hd] = __expf(se[e][hd] - smx[n][hd]) / sden[n][hd];
    }
    __syncthreads();

    // aggregate + gat bias (no expf in inner loop anymore)
    for (int idx = tid; idx < NN*DD; idx += 128) {
        int n = idx >> 7, d = idx & 127;
        int hd = d >> 5;
        float acc = 0.f;
        for (int e = 0; e < E2; e++) {
            if (sdst[e] == n)
                acc += salpha[e][hd] * sh[ssrc[e]][d];
        }
        sagg[n][d] = acc + gat_b[d];
    }

    // LN per node + mean over nodes + positional encoding (fused sum/sumsq)
    int d = tid;
    float gv = gln_g[d], bv = gln_b[d];
    float zacc = 0.f;
    for (int n = 0; n < NN; n++) {
        float v = sagg[n][d];
        float s1 = v, s2 = v * v;
        blockReduceSum2_128(s1, s2, sred);
        float mu = s1 * (1.f / DD);
        float var = s2 * (1.f / DD) - mu * mu;
        zacc += (v - mu) * rsqrtf(var + 1e-5f) * gv + bv;
    }
    zacc *= (1.f / NN);

    int t = bt % TT;
    float arg = (float)t * __expf(-(float)((d >> 1) << 1) * (logf(10000.f) / (float)DD));
    zacc += (d & 1) ? cosf(arg) : sinf(arg);
    z[(size_t)bt * DD + d] = zacc;
}

// ---------------- SGEMM with f32x2 ----------------
// 128x128 tile, K-step 16, 256 threads, 8x8 microtile, acc packed in pairs along M.
// EPI: 0 = bias, 1 = bias+relu, 2 = bias + residual + LayerNorm (requires N==128,
//      single column tile; resid read from `resid`, result to Cm).
template<int EPI>
__global__ void __launch_bounds__(256, 2)
sgemm_f32x2(const float* __restrict__ A, const float* __restrict__ Bm,
            const float* __restrict__ bias, float* __restrict__ Cm,
            const float* __restrict__ resid,
            const float* __restrict__ ln_g, const float* __restrict__ ln_b,
            int M, int N, int K)
{
    __shared__ float As[16][132];   // [k][m], padded
    __shared__ float Bs[16][132];   // [k][n], padded
    int tid = threadIdx.x;
    int tx = tid & 15, ty = tid >> 4;
    int m0 = blockIdx.y * 128, n0 = blockIdx.x * 128;

    unsigned long long acc[4][8];   // 4 m-pairs x 8 n
    #pragma unroll
    for (int i = 0; i < 4; i++)
        #pragma unroll
        for (int j = 0; j < 8; j++) acc[i][j] = 0ULL;

    for (int k0 = 0; k0 < K; k0 += 16) {
        #pragma unroll
        for (int l = 0; l < 2; l++) {
            int f = tid + l*256;
            int ma = f >> 2, kc = f & 3;
            float4 v = *(const float4*)&A[(size_t)(m0 + ma)*K + k0 + kc*4];
            As[kc*4 + 0][ma] = v.x;
            As[kc*4 + 1][ma] = v.y;
            As[kc*4 + 2][ma] = v.z;
            As[kc*4 + 3][ma] = v.w;
        }
        #pragma unroll
        for (int l = 0; l < 2; l++) {
            int f = tid + l*256;
            int kb = f >> 5, nc = f & 31;
            float4 v = *(const float4*)&Bm[(size_t)(k0 + kb)*N + n0 + nc*4];
            *(float4*)&Bs[kb][nc*4] = v;
        }
        __syncthreads();

        #pragma unroll
        for (int kk = 0; kk < 16; kk++) {
            float4 a0 = *(const float4*)&As[kk][ty*8];
            float4 a1 = *(const float4*)&As[kk][ty*8 + 4];
            float4 b0 = *(const float4*)&Bs[kk][tx*8];
            float4 b1 = *(const float4*)&Bs[kk][tx*8 + 4];
            unsigned long long a2[4];
            a2[0] = pk2(a0.x, a0.y);
            a2[1] = pk2(a0.z, a0.w);
            a2[2] = pk2(a1.x, a1.y);
            a2[3] = pk2(a1.z, a1.w);
            float bvv[8] = {b0.x, b0.y, b0.z, b0.w, b1.x, b1.y, b1.z, b1.w};
            #pragma unroll
            for (int j = 0; j < 8; j++) {
                unsigned long long b2 = pk2(bvv[j], bvv[j]);
                #pragma unroll
                for (int i = 0; i < 4; i++) fma2(acc[i][j], a2[i], b2);
            }
        }
        __syncthreads();
    }

    float bsv[8];
    #pragma unroll
    for (int j = 0; j < 8; j++) bsv[j] = bias[n0 + tx*8 + j];

    if (EPI == 2) {
        // residual + LayerNorm epilogue. N == 128, each row owned by 16 lanes
        // (consecutive lanes tx=0..15 within a half-warp) holding 8 cols each.
        float g8[8], be8[8];
        #pragma unroll
        for (int j = 0; j < 8; j++) { g8[j] = ln_g[tx*8 + j]; be8[j] = ln_b[tx*8 + j]; }
        #pragma unroll
        for (int i = 0; i < 4; i++) {
            #pragma unroll
            for (int half = 0; half < 2; half++) {
                int m = m0 + ty*8 + i*2 + half;
                const float* zr = &resid[(size_t)m*128 + tx*8];
                float4 z0 = *(const float4*)zr;
                float4 z1 = *(const float4*)(zr + 4);
                float zv[8] = {z0.x, z0.y, z0.z, z0.w, z1.x, z1.y, z1.z, z1.w};
                float v[8];
                #pragma unroll
                for (int j = 0; j < 8; j++) {
                    float lo, hi;
                    upk2(acc[i][j], lo, hi);
                    v[j] = (half ? hi : lo) + bsv[j] + zv[j];
                }
                float s = 0.f;
                #pragma unroll
                for (int j = 0; j < 8; j++) s += v[j];
                #pragma unroll
                for (int o = 1; o < 16; o <<= 1) s += __shfl_xor_sync(0xffffffffu, s, o);
                float mu = s * (1.f / 128.f);
                float q = 0.f;
                #pragma unroll
                for (int j = 0; j < 8; j++) { float dv = v[j] - mu; q += dv * dv; }
                #pragma unroll
                for (int o = 1; o < 16; o <<= 1) q += __shfl_xor_sync(0xffffffffu, q, o);
                float rstd = rsqrtf(q * (1.f / 128.f) + 1e-5f);
                float r[8];
                #pragma unroll
                for (int j = 0; j < 8; j++) r[j] = (v[j] - mu) * rstd * g8[j] + be8[j];
                float* p = &Cm[(size_t)m*128 + tx*8];
                *(float4*)p       = make_float4(r[0], r[1], r[2], r[3]);
                *(float4*)(p + 4) = make_float4(r[4], r[5], r[6], r[7]);
            }
        }
    } else {
        #pragma unroll
        for (int i = 0; i < 4; i++) {
            float r0[8], r1[8];
            #pragma unroll
            for (int j = 0; j < 8; j++) {
                float lo, hi;
                upk2(acc[i][j], lo, hi);
                float c0 = lo + bsv[j];
                float c1 = hi + bsv[j];
                if (EPI == 1) { c0 = fmaxf(c0, 0.f); c1 = fmaxf(c1, 0.f); }
                r0[j] = c0; r1[j] = c1;
            }
            int m = m0 + ty*8 + i*2;
            float* p0 = &Cm[(size_t)m*N + n0 + tx*8];
            float* p1 = &Cm[(size_t)(m+1)*N + n0 + tx*8];
            *(float4*)p0       = make_float4(r0[0], r0[1], r0[2], r0[3]);
            *(float4*)(p0 + 4) = make_float4(r0[4], r0[5], r0[6], r0[7]);
            *(float4*)p1       = make_float4(r1[0], r1[1], r1[2], r1[3]);
            *(float4*)(p1 + 4) = make_float4(r1[4], r1[5], r1[6], r1[7]);
        }
    }
}

// ---------------- attention per (b, head), 256 threads, conflict-free ------
#define QKS 36
#define SSS 76
__global__ void __launch_bounds__(256, 4)
attn_kernel(const float* __restrict__ qkv, float* __restrict__ obuf)
{
    int b = blockIdx.x;
    int h = blockIdx.y;
    int tid = threadIdx.x;  // 256

    __shared__ float sq[TT*QKS];
    __shared__ float skv[TT*QKS];   // K during S, then V
    __shared__ float sS[TT*SSS];

    const float* base = qkv + (size_t)b * TT * (3*DD) + h*DHEAD;
    for (int idx = tid; idx < TT*DHEAD; idx += 256) {
        int t = idx >> 5, d = idx & 31;
        sq[t*QKS + d]  = base[t*(3*DD)      + d];
        skv[t*QKS + d] = base[t*(3*DD) + DD + d];
    }
    __syncthreads();

    const float inv_scale = rsqrtf((float)DHEAD);
    for (int tt = tid; tt < 324; tt += 256) {
        int i0 = (tt / 18) * 4, j0 = (tt % 18) * 4;
        float acc[4][4];
        #pragma unroll
        for (int a = 0; a < 4; a++)
            #pragma unroll
            for (int c = 0; c < 4; c++) acc[a][c] = 0.f;
        #pragma unroll
        for (int d4 = 0; d4 < DHEAD; d4 += 4) {
            float4 q[4], k[4];
            #pragma unroll
            for (int a = 0; a < 4; a++) q[a] = *(const float4*)&sq[(i0+a)*QKS + d4];
            #pragma unroll
            for (int c = 0; c < 4; c++) k[c] = *(const float4*)&skv[(j0+c)*QKS + d4];
            #pragma unroll
            for (int a = 0; a < 4; a++)
                #pragma unroll
                for (int c = 0; c < 4; c++)
                    acc[a][c] += q[a].x*k[c].x + q[a].y*k[c].y + q[a].z*k[c].z + q[a].w*k[c].w;
        }
        #pragma unroll
        for (int a = 0; a < 4; a++)
            #pragma unroll
            for (int c = 0; c < 4; c++)
                sS[(i0+a)*SSS + j0 + c] = acc[a][c] * inv_scale;
    }
    __syncthreads();

    // rowwise softmax: warp per row, 8 warps
    int wid = tid >> 5, lane = tid & 31;
    for (int i = wid; i < TT; i += 8) {
        float m = -1e30f;
        for (int j = lane; j < TT; j += 32) m = fmaxf(m, sS[i*SSS + j]);
        #pragma unroll
        for (int o = 16; o > 0; o >>= 1) m = fmaxf(m, __shfl_xor_sync(0xffffffffu, m, o));
        float s = 0.f;
        for (int j = lane; j < TT; j += 32) {
            float e = __expf(sS[i*SSS + j] - m);
            sS[i*SSS + j] = e;
            s += e;
        }
        #pragma unroll
        for (int o = 16; o > 0; o >>= 1) s += __shfl_xor_sync(0xffffffffu, s, o);
        float inv = 1.f / s;
        for (int j = lane; j < TT; j += 32) sS[i*SSS + j] *= inv;
    }
    __syncthreads();

    // load V into skv (K dead)
    for (int idx = tid; idx < TT*DHEAD; idx += 256) {
        int t = idx >> 5, d = idx & 31;
        skv[t*QKS + d] = base[t*(3*DD) + 2*DD + d];
    }
    __syncthreads();

    // O = S @ V : tiles of (2 rows x 8 d), 144 tiles
    for (int tt = tid; tt < 144; tt += 256) {
        int i0 = (tt >> 2) * 2;
        int d0 = (tt & 3) * 8;
        float acc0[8], acc1[8];
        #pragma unroll
        for (int c = 0; c < 8; c++) { acc0[c] = 0.f; acc1[c] = 0.f; }
        for (int j = 0; j < TT; j++) {
            float s0 = sS[i0*SSS + j];
            float s1 = sS[(i0+1)*SSS + j];
            float4 v0 = *(const float4*)&skv[j*QKS + d0];
            float4 v1 = *(const float4*)&skv[j*QKS + d0 + 4];
            acc0[0] += s0*v0.x; acc0[1] += s0*v0.y; acc0[2] += s0*v0.z; acc0[3] += s0*v0.w;
            acc0[4] += s0*v1.x; acc0[5] += s0*v1.y; acc0[6] += s0*v1.z; acc0[7] += s0*v1.w;
            acc1[0] += s1*v0.x; acc1[1] += s1*v0.y; acc1[2] += s1*v0.z; acc1[3] += s1*v0.w;
            acc1[4] += s1*v1.x; acc1[5] += s1*v1.y; acc1[6] += s1*v1.z; acc1[7] += s1*v1.w;
        }
        float* o0 = &obuf[((size_t)b*TT + i0)*DD + h*DHEAD + d0];
        float* o1 = o0 + DD;
        *(float4*)o0       = make_float4(acc0[0], acc0[1], acc0[2], acc0[3]);
        *(float4*)(o0 + 4) = make_float4(acc0[4], acc0[5], acc0[6], acc0[7]);
        *(float4*)o1       = make_float4(acc1[0], acc1[1], acc1[2], acc1[3]);
        *(float4*)(o1 + 4) = make_float4(acc1[4], acc1[5], acc1[6], acc1[7]);
    }
}

// ---------------- 6 MLP heads on last timestep ----------------
__global__ void heads_kernel(const float* __restrict__ z,
                             const float* __restrict__ hw1, const float* __restrict__ hb1,
                             const float* __restrict__ hw2, const float* __restrict__ hb2,
                             float* __restrict__ out)
{
    int b = blockIdx.x;
    int k = blockIdx.y;
    int tid = threadIdx.x;  // 64
    __shared__ float slast[DD];
    __shared__ float sh1[64];
    const float* zr = z + ((size_t)b*TT + (TT-1))*DD;
    slast[tid] = zr[tid];
    slast[tid + 64] = zr[tid + 64];
    __syncthreads();

    float acc = hb1[k*64 + tid];
    const float* w1 = hw1 + (size_t)k*DD*64;
    #pragma unroll 8
    for (int d = 0; d < DD; d++) acc += slast[d] * w1[d*64 + tid];
    sh1[tid] = fmaxf(acc, 0.f);
    __syncthreads();

    if (tid < 5) {
        float a2 = hb2[k*5 + tid];
        const float* w2 = hw2 + (size_t)k*64*5;
        #pragma unroll 8
        for (int m = 0; m < 64; m++) a2 += sh1[m] * w2[m*5 + tid];
        out[((size_t)k*BB + b)*5 + tid] = a2;
    }
}

// ---------------- launcher ----------------
extern "C" void kernel_launch(void* const* d_in, const int* in_sizes, int n_in,
                              void* d_out, int out_size)
{
    const float* x        = (const float*)d_in[0];
    const int*   ei       = (const int*)  d_in[1];
    const float* gcn_w    = (const float*)d_in[2];
    const float* gcn_b    = (const float*)d_in[3];
    const float* gat_w    = (const float*)d_in[4];
    const float* gat_a_s  = (const float*)d_in[5];
    const float* gat_a_d  = (const float*)d_in[6];
    const float* gat_b    = (const float*)d_in[7];
    const float* gln_g    = (const float*)d_in[8];
    const float* gln_b    = (const float*)d_in[9];
    const float* tw_qkv   = (const float*)d_in[10];
    const float* tb_qkv   = (const float*)d_in[11];
    const float* tw_o     = (const float*)d_in[12];
    const float* tb_o     = (const float*)d_in[13];
    const float* ln1_g    = (const float*)d_in[14];
    const float* ln1_b    = (const float*)d_in[15];
    const float* w_ff1    = (const float*)d_in[16];
    const float* b_ff1    = (const float*)d_in[17];
    const float* w_ff2    = (const float*)d_in[18];
    const float* b_ff2    = (const float*)d_in[19];
    const float* ln2_g    = (const float*)d_in[20];
    const float* ln2_b    = (const float*)d_in[21];
    const float* hw1      = (const float*)d_in[22];
    const float* hb1      = (const float*)d_in[23];
    const float* hw2      = (const float*)d_in[24];
    const float* hb2      = (const float*)d_in[25];
    float* out = (float*)d_out;

    float *zp, *qkvp, *op, *ffp;
    cudaGetSymbolAddress((void**)&zp,   d_z);
    cudaGetSymbolAddress((void**)&qkvp, d_qkv);
    cudaGetSymbolAddress((void**)&op,   d_o);
    cudaGetSymbolAddress((void**)&ffp,  d_ff);

    int E = in_sizes[1] / 2;

    build_graph_kernel<<<1, 32>>>(ei, E);

    gcn_gat_kernel<<<BT, 128>>>(x, gcn_w, gcn_b, gat_w, gat_a_s, gat_a_d,
                                gat_b, gln_g, gln_b, zp, E + NN);

    for (int i = 0; i < 3; i++) {
        // qkv = z @ Wqkv + b      (18432 x 384)
        sgemm_f32x2<0><<<dim3((3*DD)/128, BT/128), 256>>>(
            zp, tw_qkv + (size_t)i*DD*3*DD, tb_qkv + (size_t)i*3*DD, qkvp,
            nullptr, nullptr, nullptr, BT, 3*DD, DD);
        // attention
        attn_kernel<<<dim3(BB, NHEAD), 256>>>(qkvp, op);
        // z = LN(z + o @ Wo + b)  — fused epilogue
        sgemm_f32x2<2><<<dim3(1, BT/128), 256>>>(
            op, tw_o + (size_t)i*DD*DD, tb_o + (size_t)i*DD, zp,
            zp, ln1_g + (size_t)i*DD, ln1_b + (size_t)i*DD, BT, DD, DD);
        // ff1 = relu(z @ W1 + b1)
        sgemm_f32x2<1><<<dim3(FFD/128, BT/128), 256>>>(
            zp, w_ff1 + (size_t)i*DD*FFD, b_ff1 + (size_t)i*FFD, ffp,
            nullptr, nullptr, nullptr, BT, FFD, DD);
        // z = LN(z + ff1 @ W2 + b2) — fused epilogue
        sgemm_f32x2<2><<<dim3(1, BT/128), 256>>>(
            ffp, w_ff2 + (size_t)i*FFD*DD, b_ff2 + (size_t)i*DD, zp,
            zp, ln2_g + (size_t)i*DD, ln2_b + (size_t)i*DD, BT, DD, FFD);
    }

    heads_kernel<<<dim3(BB, 6), 64>>>(zp, hw1, hb1, hw2, hb2, out);
}

// round 4
// speedup vs baseline: 1.9590x; 1.2413x over previous
#include <cuda_runtime.h>
#include <math.h>
#include <stdint.h>

// Problem constants (fixed by reference)
#define BB 256
#define TT 72
#define NN 5
#define FF_IN 10
#define HH 4
#define CC 32
#define DD 128
#define FFD 256
#define NHEAD 4
#define DHEAD 32
#define BT (BB*TT)   // 18432

// ---------------- device scratch (no allocations allowed) ----------------
__device__ float d_z[BT*DD];
__device__ float d_qkv[BT*3*DD];
__device__ float d_o[BT*DD];
__device__ float d_ff[BT*FFD];
__device__ float d_Anorm[NN*NN];
__device__ int   d_src2[64];
__device__ int   d_dst2[64];

// ---------------- tf32 helpers ----------------
__device__ __forceinline__ uint32_t to_tf32(float x) {
    uint32_t r;
    asm("cvt.rna.tf32.f32 %0, %1;" : "=r"(r) : "f"(x));
    return r;
}
__device__ __forceinline__ void mma_tf32(float* d, const uint32_t* a, const uint32_t* b) {
    asm volatile(
        "mma.sync.aligned.m16n8k8.row.col.f32.tf32.tf32.f32 "
        "{%0,%1,%2,%3}, {%4,%5,%6,%7}, {%8,%9}, {%0,%1,%2,%3};"
        : "+f"(d[0]), "+f"(d[1]), "+f"(d[2]), "+f"(d[3])
        : "r"(a[0]), "r"(a[1]), "r"(a[2]), "r"(a[3]), "r"(b[0]), "r"(b[1]));
}

// ---------------- graph build (single thread, trivial) ----------------
__global__ void build_graph_kernel(const int* __restrict__ ei, int E) {
    if (threadIdx.x != 0 || blockIdx.x != 0) return;
    float A[NN][NN];
    for (int i = 0; i < NN*NN; i++) ((float*)A)[i] = 0.f;
    for (int e = 0; e < E; e++) {
        int s = ei[e];
        int d = ei[E + e];
        A[d][s] += 1.f;
        d_src2[e] = s; d_dst2[e] = d;
    }
    for (int n = 0; n < NN; n++) {
        A[n][n] += 1.f;
        d_src2[E + n] = n; d_dst2[E + n] = n;
    }
    float dinv[NN];
    for (int n = 0; n < NN; n++) {
        float s = 0.f;
        for (int j = 0; j < NN; j++) s += A[n][j];
        dinv[n] = (s > 0.f) ? (1.f / sqrtf(s)) : 0.f;
    }
    for (int i = 0; i < NN; i++)
        for (int j = 0; j < NN; j++)
            d_Anorm[i*NN + j] = dinv[i] * A[i][j] * dinv[j];
}

// ---------------- fused dual block reduce (128 threads) ----------------
__device__ __forceinline__ void blockReduceSum2_128(float &a, float &b, float* sred) {
    __syncthreads();
    #pragma unroll
    for (int o = 16; o > 0; o >>= 1) {
        a += __shfl_xor_sync(0xffffffffu, a, o);
        b += __shfl_xor_sync(0xffffffffu, b, o);
    }
    if ((threadIdx.x & 31) == 0) {
        int w = threadIdx.x >> 5;
        sred[w] = a; sred[4 + w] = b;
    }
    __syncthreads();
    a = sred[0] + sred[1] + sred[2] + sred[3];
    b = sred[4] + sred[5] + sred[6] + sred[7];
}

// ---------------- fused GCN + GAT + LN + node-mean + PE ----------------
__global__ void gcn_gat_kernel(
    const float* __restrict__ x,
    const float* __restrict__ gcn_w, const float* __restrict__ gcn_b,
    const float* __restrict__ gat_w, const float* __restrict__ a_src,
    const float* __restrict__ a_dst, const float* __restrict__ gat_b,
    const float* __restrict__ gln_g, const float* __restrict__ gln_b,
    float* __restrict__ z, int E2)
{
    int bt = blockIdx.x;
    int tid = threadIdx.x;  // 128

    __shared__ float sx[NN][FF_IN];
    __shared__ float sxw[NN][64];
    __shared__ float sgcn[NN][64];
    __shared__ float sh[NN][DD];
    __shared__ float sagg[NN][DD];
    __shared__ float sas[NN][HH], sad[NN][HH];
    __shared__ float se[32][HH];
    __shared__ float salpha[32][HH];
    __shared__ float smx[NN][HH], sden[NN][HH];
    __shared__ float sAn[NN*NN];
    __shared__ int   ssrc[32], sdst[32];
    __shared__ float sred[8];

    const float* xp = x + (size_t)bt * NN * FF_IN;
    if (tid < NN*FF_IN) ((float*)sx)[tid] = xp[tid];
    if (tid < NN*NN) sAn[tid] = d_Anorm[tid];
    if (tid < E2) { ssrc[tid] = d_src2[tid]; sdst[tid] = d_dst2[tid]; }
    __syncthreads();

    for (int idx = tid; idx < NN*64; idx += 128) {
        int n = idx >> 6, c = idx & 63;
        float acc = gcn_b[c];
        #pragma unroll
        for (int f = 0; f < FF_IN; f++) acc += sx[n][f] * gcn_w[f*64 + c];
        sxw[n][c] = acc;
    }
    __syncthreads();

    for (int idx = tid; idx < NN*64; idx += 128) {
        int n = idx >> 6, c = idx & 63;
        float acc = 0.f;
        #pragma unroll
        for (int m = 0; m < NN; m++) acc += sAn[n*NN + m] * sxw[m][c];
        sgcn[n][c] = tanhf(acc);
    }
    __syncthreads();

    for (int idx = tid; idx < NN*DD; idx += 128) {
        int n = idx >> 7, d = idx & 127;
        float acc = 0.f;
        #pragma unroll 8
        for (int f = 0; f < 64; f++) acc += sgcn[n][f] * gat_w[f*DD + d];
        sh[n][d] = acc;
    }
    __syncthreads();

    if (tid < NN*HH*2) {
        int n = tid / (HH*2), r = tid % (HH*2), hd = r >> 1, which = r & 1;
        const float* av = which ? a_dst : a_src;
        float acc = 0.f;
        #pragma unroll
        for (int c = 0; c < CC; c++) acc += sh[n][hd*CC + c] * av[hd*CC + c];
        if (which) sad[n][hd] = acc; else sas[n][hd] = acc;
    }
    __syncthreads();

    for (int idx = tid; idx < E2*HH; idx += 128) {
        int e = idx >> 2, hd = idx & 3;
        float v = sas[ssrc[e]][hd] + sad[sdst[e]][hd];
        se[e][hd] = (v > 0.f) ? v : 0.2f * v;
    }
    __syncthreads();

    if (tid < NN*HH) {
        int n = tid >> 2, hd = tid & 3;
        float m = -1e30f;
        for (int e = 0; e < E2; e++) if (sdst[e] == n) m = fmaxf(m, se[e][hd]);
        float s = 0.f;
        for (int e = 0; e < E2; e++) if (sdst[e] == n) s += __expf(se[e][hd] - m);
        smx[n][hd] = m; sden[n][hd] = s;
    }
    __syncthreads();

    for (int idx = tid; idx < E2*HH; idx += 128) {
        int e = idx >> 2, hd = idx & 3;
        int n = sdst[e];
        salpha[e][hd] = __expf(se[e][hd] - smx[n][hd]) / sden[n][hd];
    }
    __syncthreads();

    for (int idx = tid; idx < NN*DD; idx += 128) {
        int n = idx >> 7, d = idx & 127;
        int hd = d >> 5;
        float acc = 0.f;
        for (int e = 0; e < E2; e++) {
            if (sdst[e] == n)
                acc += salpha[e][hd] * sh[ssrc[e]][d];
        }
        sagg[n][d] = acc + gat_b[d];
    }

    int d = tid;
    float gv = gln_g[d], bv = gln_b[d];
    float zacc = 0.f;
    for (int n = 0; n < NN; n++) {
        float v = sagg[n][d];
        float s1 = v, s2 = v * v;
        blockReduceSum2_128(s1, s2, sred);
        float mu = s1 * (1.f / DD);
        float var = s2 * (1.f / DD) - mu * mu;
        zacc += (v - mu) * rsqrtf(var + 1e-5f) * gv + bv;
    }
    zacc *= (1.f / NN);

    int t = bt % TT;
    float arg = (float)t * __expf(-(float)((d >> 1) << 1) * (logf(10000.f) / (float)DD));
    zacc += (d & 1) ? cosf(arg) : sinf(arg);
    z[(size_t)bt * DD + d] = zacc;
}

// ---------------- tf32 tensor-core GEMM ----------------
// C = A(MxK) @ B(KxN) + bias. 128x128 block tile, 8 warps (2x4), 64x32 warp tile,
// m16n8k8 tf32 mma, K-step 16, smem stride 136 (conflict-free fragment loads).
// EPI: 0 = bias, 1 = bias+relu, 2 = bias + residual + LayerNorm (N==128 only).
#define TFS 136
template<int EPI>
__global__ void __launch_bounds__(256)
gemm_tf32(const float* __restrict__ A, const float* __restrict__ Bm,
          const float* __restrict__ bias, float* __restrict__ Cm,
          const float* __restrict__ resid,
          const float* __restrict__ ln_g, const float* __restrict__ ln_b,
          int M, int N, int K)
{
    extern __shared__ char smem_raw[];
    uint32_t* As = (uint32_t*)smem_raw;          // [16][TFS]
    uint32_t* Bs = As + 16*TFS;                  // [16][TFS]

    int tid = threadIdx.x;
    int warp = tid >> 5, lane = tid & 31;
    int tig = lane & 3, grp = lane >> 2;
    int wm = warp >> 2, wn = warp & 3;           // 2 x 4 warps
    int m0 = blockIdx.y * 128, n0 = blockIdx.x * 128;

    float acc[4][4][4];
    #pragma unroll
    for (int i = 0; i < 4; i++)
        #pragma unroll
        for (int j = 0; j < 4; j++)
            #pragma unroll
            for (int c = 0; c < 4; c++) acc[i][j][c] = 0.f;

    for (int k0 = 0; k0 < K; k0 += 16) {
        // stage A (transposed to [k][m], tf32)
        #pragma unroll
        for (int l = 0; l < 2; l++) {
            int f = tid + l*256;
            int ma = f >> 2, kc = f & 3;
            float4 v = *(const float4*)&A[(size_t)(m0 + ma)*K + k0 + kc*4];
            As[(kc*4 + 0)*TFS + ma] = to_tf32(v.x);
            As[(kc*4 + 1)*TFS + ma] = to_tf32(v.y);
            As[(kc*4 + 2)*TFS + ma] = to_tf32(v.z);
            As[(kc*4 + 3)*TFS + ma] = to_tf32(v.w);
        }
        // stage B ([k][n], tf32)
        #pragma unroll
        for (int l = 0; l < 2; l++) {
            int f = tid + l*256;
            int kb = f >> 5, nc = f & 31;
            float4 v = *(const float4*)&Bm[(size_t)(k0 + kb)*N + n0 + nc*4];
            uint32_t* p = &Bs[kb*TFS + nc*4];
            p[0] = to_tf32(v.x); p[1] = to_tf32(v.y);
            p[2] = to_tf32(v.z); p[3] = to_tf32(v.w);
        }
        __syncthreads();

        #pragma unroll
        for (int ks = 0; ks < 2; ks++) {
            int kb = ks*8;
            uint32_t afr[4][4];
            #pragma unroll
            for (int mf = 0; mf < 4; mf++) {
                int r0 = wm*64 + mf*16 + grp;
                afr[mf][0] = As[(kb + tig)*TFS + r0];
                afr[mf][1] = As[(kb + tig)*TFS + r0 + 8];
                afr[mf][2] = As[(kb + tig + 4)*TFS + r0];
                afr[mf][3] = As[(kb + tig + 4)*TFS + r0 + 8];
            }
            uint32_t bfr[4][2];
            #pragma unroll
            for (int nf = 0; nf < 4; nf++) {
                int c0 = wn*32 + nf*8 + grp;
                bfr[nf][0] = Bs[(kb + tig)*TFS + c0];
                bfr[nf][1] = Bs[(kb + tig + 4)*TFS + c0];
            }
            #pragma unroll
            for (int mf = 0; mf < 4; mf++)
                #pragma unroll
                for (int nf = 0; nf < 4; nf++)
                    mma_tf32(acc[mf][nf], afr[mf], bfr[nf]);
        }
        __syncthreads();
    }

    if (EPI == 2) {
        // Stage C into smem [128][132], then row-wise residual+LN (N==128, n0==0).
        float* Cs = (float*)smem_raw;            // [128][132]
        #pragma unroll
        for (int mf = 0; mf < 4; mf++) {
            int r = wm*64 + mf*16 + grp;
            #pragma unroll
            for (int nf = 0; nf < 4; nf++) {
                int c = wn*32 + nf*8 + 2*tig;
                Cs[r*132 + c]           = acc[mf][nf][0];
                Cs[r*132 + c + 1]       = acc[mf][nf][1];
                Cs[(r + 8)*132 + c]     = acc[mf][nf][2];
                Cs[(r + 8)*132 + c + 1] = acc[mf][nf][3];
            }
        }
        __syncthreads();

        float4 bb = *(const float4*)&bias[lane*4];
        float4 gg = *(const float4*)&ln_g[lane*4];
        float4 be = *(const float4*)&ln_b[lane*4];
        for (int r = warp*16; r < warp*16 + 16; r++) {
            int m = m0 + r;
            float4 cv = *(const float4*)&Cs[r*132 + lane*4];
            float4 zv = *(const float4*)&resid[(size_t)m*128 + lane*4];
            float v[4] = {cv.x + bb.x + zv.x, cv.y + bb.y + zv.y,
                          cv.z + bb.z + zv.z, cv.w + bb.w + zv.w};
            float s = v[0] + v[1] + v[2] + v[3];
            #pragma unroll
            for (int o = 16; o > 0; o >>= 1) s += __shfl_xor_sync(0xffffffffu, s, o);
            float mu = s * (1.f / 128.f);
            float q = 0.f;
            #pragma unroll
            for (int j = 0; j < 4; j++) { float dv = v[j] - mu; q += dv * dv; }
            #pragma unroll
            for (int o = 16; o > 0; o >>= 1) q += __shfl_xor_sync(0xffffffffu, q, o);
            float rstd = rsqrtf(q * (1.f / 128.f) + 1e-5f);
            float4 rv;
            rv.x = (v[0] - mu) * rstd * gg.x + be.x;
            rv.y = (v[1] - mu) * rstd * gg.y + be.y;
            rv.z = (v[2] - mu) * rstd * gg.z + be.z;
            rv.w = (v[3] - mu) * rstd * gg.w + be.w;
            *(float4*)&Cm[(size_t)m*128 + lane*4] = rv;
        }
    } else {
        #pragma unroll
        for (int mf = 0; mf < 4; mf++) {
            int r = m0 + wm*64 + mf*16 + grp;
            #pragma unroll
            for (int nf = 0; nf < 4; nf++) {
                int c = n0 + wn*32 + nf*8 + 2*tig;
                float b0 = bias[c], b1 = bias[c + 1];
                float v0 = acc[mf][nf][0] + b0;
                float v1 = acc[mf][nf][1] + b1;
                float v2 = acc[mf][nf][2] + b0;
                float v3 = acc[mf][nf][3] + b1;
                if (EPI == 1) {
                    v0 = fmaxf(v0, 0.f); v1 = fmaxf(v1, 0.f);
                    v2 = fmaxf(v2, 0.f); v3 = fmaxf(v3, 0.f);
                }
                *(float2*)&Cm[(size_t)r*N + c]       = make_float2(v0, v1);
                *(float2*)&Cm[(size_t)(r + 8)*N + c] = make_float2(v2, v3);
            }
        }
    }
}

// ---------------- attention per (b, head), 256 threads, conflict-free ------
#define QKS 36
#define SSS 76
__global__ void __launch_bounds__(256, 4)
attn_kernel(const float* __restrict__ qkv, float* __restrict__ obuf)
{
    int b = blockIdx.x;
    int h = blockIdx.y;
    int tid = threadIdx.x;  // 256

    __shared__ float sq[TT*QKS];
    __shared__ float skv[TT*QKS];
    __shared__ float sS[TT*SSS];

    const float* base = qkv + (size_t)b * TT * (3*DD) + h*DHEAD;
    for (int idx = tid; idx < TT*DHEAD; idx += 256) {
        int t = idx >> 5, d = idx & 31;
        sq[t*QKS + d]  = base[t*(3*DD)      + d];
        skv[t*QKS + d] = base[t*(3*DD) + DD + d];
    }
    __syncthreads();

    const float inv_scale = rsqrtf((float)DHEAD);
    for (int tt = tid; tt < 324; tt += 256) {
        int i0 = (tt / 18) * 4, j0 = (tt % 18) * 4;
        float acc[4][4];
        #pragma unroll
        for (int a = 0; a < 4; a++)
            #pragma unroll
            for (int c = 0; c < 4; c++) acc[a][c] = 0.f;
        #pragma unroll
        for (int d4 = 0; d4 < DHEAD; d4 += 4) {
            float4 q[4], k[4];
            #pragma unroll
            for (int a = 0; a < 4; a++) q[a] = *(const float4*)&sq[(i0+a)*QKS + d4];
            #pragma unroll
            for (int c = 0; c < 4; c++) k[c] = *(const float4*)&skv[(j0+c)*QKS + d4];
            #pragma unroll
            for (int a = 0; a < 4; a++)
                #pragma unroll
                for (int c = 0; c < 4; c++)
                    acc[a][c] += q[a].x*k[c].x + q[a].y*k[c].y + q[a].z*k[c].z + q[a].w*k[c].w;
        }
        #pragma unroll
        for (int a = 0; a < 4; a++)
            #pragma unroll
            for (int c = 0; c < 4; c++)
                sS[(i0+a)*SSS + j0 + c] = acc[a][c] * inv_scale;
    }
    __syncthreads();

    int wid = tid >> 5, lane = tid & 31;
    for (int i = wid; i < TT; i += 8) {
        float m = -1e30f;
        for (int j = lane; j < TT; j += 32) m = fmaxf(m, sS[i*SSS + j]);
        #pragma unroll
        for (int o = 16; o > 0; o >>= 1) m = fmaxf(m, __shfl_xor_sync(0xffffffffu, m, o));
        float s = 0.f;
        for (int j = lane; j < TT; j += 32) {
            float e = __expf(sS[i*SSS + j] - m);
            sS[i*SSS + j] = e;
            s += e;
        }
        #pragma unroll
        for (int o = 16; o > 0; o >>= 1) s += __shfl_xor_sync(0xffffffffu, s, o);
        float inv = 1.f / s;
        for (int j = lane; j < TT; j += 32) sS[i*SSS + j] *= inv;
    }
    __syncthreads();

    for (int idx = tid; idx < TT*DHEAD; idx += 256) {
        int t = idx >> 5, d = idx & 31;
        skv[t*QKS + d] = base[t*(3*DD) + 2*DD + d];
    }
    __syncthreads();

    for (int tt = tid; tt < 144; tt += 256) {
        int i0 = (tt >> 2) * 2;
        int d0 = (tt & 3) * 8;
        float acc0[8], acc1[8];
        #pragma unroll
        for (int c = 0; c < 8; c++) { acc0[c] = 0.f; acc1[c] = 0.f; }
        for (int j = 0; j < TT; j++) {
            float s0 = sS[i0*SSS + j];
            float s1 = sS[(i0+1)*SSS + j];
            float4 v0 = *(const float4*)&skv[j*QKS + d0];
            float4 v1 = *(const float4*)&skv[j*QKS + d0 + 4];
            acc0[0] += s0*v0.x; acc0[1] += s0*v0.y; acc0[2] += s0*v0.z; acc0[3] += s0*v0.w;
            acc0[4] += s0*v1.x; acc0[5] += s0*v1.y; acc0[6] += s0*v1.z; acc0[7] += s0*v1.w;
            acc1[0] += s1*v0.x; acc1[1] += s1*v0.y; acc1[2] += s1*v0.z; acc1[3] += s1*v0.w;
            acc1[4] += s1*v1.x; acc1[5] += s1*v1.y; acc1[6] += s1*v1.z; acc1[7] += s1*v1.w;
        }
        float* o0 = &obuf[((size_t)b*TT + i0)*DD + h*DHEAD + d0];
        float* o1 = o0 + DD;
        *(float4*)o0       = make_float4(acc0[0], acc0[1], acc0[2], acc0[3]);
        *(float4*)(o0 + 4) = make_float4(acc0[4], acc0[5], acc0[6], acc0[7]);
        *(float4*)o1       = make_float4(acc1[0], acc1[1], acc1[2], acc1[3]);
        *(float4*)(o1 + 4) = make_float4(acc1[4], acc1[5], acc1[6], acc1[7]);
    }
}

// ---------------- 6 MLP heads on last timestep ----------------
__global__ void heads_kernel(const float* __restrict__ z,
                             const float* __restrict__ hw1, const float* __restrict__ hb1,
                             const float* __restrict__ hw2, const float* __restrict__ hb2,
                             float* __restrict__ out)
{
    int b = blockIdx.x;
    int k = blockIdx.y;
    int tid = threadIdx.x;  // 64
    __shared__ float slast[DD];
    __shared__ float sh1[64];
    const float* zr = z + ((size_t)b*TT + (TT-1))*DD;
    slast[tid] = zr[tid];
    slast[tid + 64] = zr[tid + 64];
    __syncthreads();

    float acc = hb1[k*64 + tid];
    const float* w1 = hw1 + (size_t)k*DD*64;
    #pragma unroll 8
    for (int d = 0; d < DD; d++) acc += slast[d] * w1[d*64 + tid];
    sh1[tid] = fmaxf(acc, 0.f);
    __syncthreads();

    if (tid < 5) {
        float a2 = hb2[k*5 + tid];
        const float* w2 = hw2 + (size_t)k*64*5;
        #pragma unroll 8
        for (int m = 0; m < 64; m++) a2 += sh1[m] * w2[m*5 + tid];
        out[((size_t)k*BB + b)*5 + tid] = a2;
    }
}

// ---------------- launcher ----------------
extern "C" void kernel_launch(void* const* d_in, const int* in_sizes, int n_in,
                              void* d_out, int out_size)
{
    const float* x        = (const float*)d_in[0];
    const int*   ei       = (const int*)  d_in[1];
    const float* gcn_w    = (const float*)d_in[2];
    const float* gcn_b    = (const float*)d_in[3];
    const float* gat_w    = (const float*)d_in[4];
    const float* gat_a_s  = (const float*)d_in[5];
    const float* gat_a_d  = (const float*)d_in[6];
    const float* gat_b    = (const float*)d_in[7];
    const float* gln_g    = (const float*)d_in[8];
    const float* gln_b    = (const float*)d_in[9];
    const float* tw_qkv   = (const float*)d_in[10];
    const float* tb_qkv   = (const float*)d_in[11];
    const float* tw_o     = (const float*)d_in[12];
    const float* tb_o     = (const float*)d_in[13];
    const float* ln1_g    = (const float*)d_in[14];
    const float* ln1_b    = (const float*)d_in[15];
    const float* w_ff1    = (const float*)d_in[16];
    const float* b_ff1    = (const float*)d_in[17];
    const float* w_ff2    = (const float*)d_in[18];
    const float* b_ff2    = (const float*)d_in[19];
    const float* ln2_g    = (const float*)d_in[20];
    const float* ln2_b    = (const float*)d_in[21];
    const float* hw1      = (const float*)d_in[22];
    const float* hb1      = (const float*)d_in[23];
    const float* hw2      = (const float*)d_in[24];
    const float* hb2      = (const float*)d_in[25];
    float* out = (float*)d_out;

    float *zp, *qkvp, *op, *ffp;
    cudaGetSymbolAddress((void**)&zp,   d_z);
    cudaGetSymbolAddress((void**)&qkvp, d_qkv);
    cudaGetSymbolAddress((void**)&op,   d_o);
    cudaGetSymbolAddress((void**)&ffp,  d_ff);

    const int SMEM_MAIN = 2 * 16 * TFS * 4;       // 17408 B
    const int SMEM_EPI2 = 128 * 132 * 4;          // 67584 B
    cudaFuncSetAttribute(gemm_tf32<2>, cudaFuncAttributeMaxDynamicSharedMemorySize, SMEM_EPI2);

    int E = in_sizes[1] / 2;

    build_graph_kernel<<<1, 32>>>(ei, E);

    gcn_gat_kernel<<<BT, 128>>>(x, gcn_w, gcn_b, gat_w, gat_a_s, gat_a_d,
                                gat_b, gln_g, gln_b, zp, E + NN);

    for (int i = 0; i < 3; i++) {
        // qkv = z @ Wqkv + b      (18432 x 384, K=128)
        gemm_tf32<0><<<dim3((3*DD)/128, BT/128), 256, SMEM_MAIN>>>(
            zp, tw_qkv + (size_t)i*DD*3*DD, tb_qkv + (size_t)i*3*DD, qkvp,
            nullptr, nullptr, nullptr, BT, 3*DD, DD);
        // attention
        attn_kernel<<<dim3(BB, NHEAD), 256>>>(qkvp, op);
        // z = LN(z + o @ Wo + b)  — fused epilogue
        gemm_tf32<2><<<dim3(1, BT/128), 256, SMEM_EPI2>>>(
            op, tw_o + (size_t)i*DD*DD, tb_o + (size_t)i*DD, zp,
            zp, ln1_g + (size_t)i*DD, ln1_b + (size_t)i*DD, BT, DD, DD);
        // ff1 = relu(z @ W1 + b1)
        gemm_tf32<1><<<dim3(FFD/128, BT/128), 256, SMEM_MAIN>>>(
            zp, w_ff1 + (size_t)i*DD*FFD, b_ff1 + (size_t)i*FFD, ffp,
            nullptr, nullptr, nullptr, BT, FFD, DD);
        // z = LN(z + ff1 @ W2 + b2) — fused epilogue (K=256)
        gemm_tf32<2><<<dim3(1, BT/128), 256, SMEM_EPI2>>>(
            ffp, w_ff2 + (size_t)i*FFD*DD, b_ff2 + (size_t)i*DD, zp,
            zp, ln2_g + (size_t)i*DD, ln2_b + (size_t)i*DD, BT, DD, FFD);
    }

    heads_kernel<<<dim3(BB, 6), 64>>>(zp, hw1, hb1, hw2, hb2, out);
}